// round 1
// baseline (speedup 1.0000x reference)
#include <cuda_runtime.h>
#include <cuda_bf16.h>
#include <math.h>

// Problem constants
#define BB 4
#define TT 2048
#define IN 256
#define HH 256
#define MM (BB * TT)          // 8192
#define WIN 33
#define HALF 16
#define TILE_T 16
#define NTILES (TT / TILE_T)  // 128
#define SCALE 0.0625f         // 256^-0.5
#define EPS 1e-5f

// Scratch (device globals: allowed by harness rules)
__device__ float g_y[3][MM * HH];            // q,k,v pre-norm activations (24 MB)
__device__ float g_mean[3][BB * HH];
__device__ float g_rstd[3][BB * HH];
__device__ float g_partial[BB * NTILES * HH]; // per-tile partial sums of attention output

// ---------------------------------------------------------------------------
// Kernel 1: y[s] = x @ W[s].T + b[s]   (s = 0:q, 1:k, 2:v)
// 64x64 block tile, K-step 16, 4x4 per-thread microtile.
// ---------------------------------------------------------------------------
__global__ __launch_bounds__(256) void gemm_qkv_kernel(
    const float* __restrict__ x,
    const float* __restrict__ Wq, const float* __restrict__ bq,
    const float* __restrict__ Wk, const float* __restrict__ bk,
    const float* __restrict__ Wv, const float* __restrict__ bv)
{
    const int s = blockIdx.z;
    const float* W    = (s == 0) ? Wq : (s == 1) ? Wk : Wv;
    const float* bias = (s == 0) ? bq : (s == 1) ? bk : bv;
    float* y = g_y[s];

    __shared__ float a_s[16][68];
    __shared__ float w_s[16][68];

    const int m0 = blockIdx.x * 64;
    const int n0 = blockIdx.y * 64;
    const int tid = threadIdx.x;

    const int tm = (tid >> 4) << 2;  // 0..60
    const int tn = (tid & 15) << 2;  // 0..60

    const int lr = tid >> 2;         // 0..63 (row in tile for loads)
    const int lc = (tid & 3) << 2;   // 0,4,8,12 (k offset for loads)

    float acc[4][4] = {};

    #pragma unroll 1
    for (int k0 = 0; k0 < IN; k0 += 16) {
        float4 av = *(const float4*)&x[(size_t)(m0 + lr) * IN + k0 + lc];
        float4 wv = *(const float4*)&W[(size_t)(n0 + lr) * IN + k0 + lc];
        a_s[lc + 0][lr] = av.x; a_s[lc + 1][lr] = av.y;
        a_s[lc + 2][lr] = av.z; a_s[lc + 3][lr] = av.w;
        w_s[lc + 0][lr] = wv.x; w_s[lc + 1][lr] = wv.y;
        w_s[lc + 2][lr] = wv.z; w_s[lc + 3][lr] = wv.w;
        __syncthreads();
        #pragma unroll
        for (int kk = 0; kk < 16; kk++) {
            float4 a = *(float4*)&a_s[kk][tm];
            float4 b = *(float4*)&w_s[kk][tn];
            float ar[4] = {a.x, a.y, a.z, a.w};
            float br[4] = {b.x, b.y, b.z, b.w};
            #pragma unroll
            for (int i = 0; i < 4; i++)
                #pragma unroll
                for (int j = 0; j < 4; j++)
                    acc[i][j] = fmaf(ar[i], br[j], acc[i][j]);
        }
        __syncthreads();
    }

    const float b0 = bias[n0 + tn + 0];
    const float b1 = bias[n0 + tn + 1];
    const float b2 = bias[n0 + tn + 2];
    const float b3 = bias[n0 + tn + 3];
    #pragma unroll
    for (int i = 0; i < 4; i++) {
        float4 o = make_float4(acc[i][0] + b0, acc[i][1] + b1,
                               acc[i][2] + b2, acc[i][3] + b3);
        *(float4*)&y[(size_t)(m0 + tm + i) * HH + n0 + tn] = o;
    }
}

// ---------------------------------------------------------------------------
// Kernel 2: per-(b,h) mean / rstd over T for each of q,k,v.
// grid = (3, B, H/64), block = 256 = 64 h-columns x 4 t-groups.
// ---------------------------------------------------------------------------
__global__ __launch_bounds__(256) void stats_kernel()
{
    const int s  = blockIdx.x;
    const int b  = blockIdx.y;
    const int h0 = blockIdx.z * 64;
    const int ht = threadIdx.x & 63;
    const int tg = threadIdx.x >> 6;   // 0..3

    const float* y = g_y[s] + (size_t)b * TT * HH;
    float sum = 0.f, sq = 0.f;
    for (int t = tg; t < TT; t += 4) {
        float v = y[(size_t)t * HH + h0 + ht];
        sum += v;
        sq  = fmaf(v, v, sq);
    }
    __shared__ float ssum[4][64], ssq[4][64];
    ssum[tg][ht] = sum;
    ssq[tg][ht]  = sq;
    __syncthreads();
    if (tg == 0) {
        float S = ssum[0][ht] + ssum[1][ht] + ssum[2][ht] + ssum[3][ht];
        float Q = ssq[0][ht]  + ssq[1][ht]  + ssq[2][ht]  + ssq[3][ht];
        float m   = S * (1.0f / TT);
        float var = Q * (1.0f / TT) - m * m;
        g_mean[s][b * HH + h0 + ht] = m;
        g_rstd[s][b * HH + h0 + ht] = rsqrtf(var + EPS);
    }
}

// ---------------------------------------------------------------------------
// Kernel 3: fused normalize + windowed attention + per-tile partial mean.
// grid = (T/16, B), block = 256, dynamic smem ~123 KB.
// ---------------------------------------------------------------------------
__global__ __launch_bounds__(256) void attn_kernel()
{
    extern __shared__ float sm[];
    float* k_s  = sm;                    // 48*256
    float* v_s  = sm + 48 * 256;         // 48*256
    float* q_s  = sm + 96 * 256;         // 16*256
    float* sc   = sm + 112 * 256;        // 16*36
    float* st   = sc + 16 * 36;          // 6*256
    float* mq_s = st;         float* rq_s = st + 256;
    float* mk_s = st + 512;   float* rk_s = st + 768;
    float* mv_s = st + 1024;  float* rv_s = st + 1280;

    const int tile = blockIdx.x;
    const int b    = blockIdx.y;
    const int t0   = tile * TILE_T;
    const int tid  = threadIdx.x;

    {
        int off = b * HH + tid;
        mq_s[tid] = g_mean[0][off]; rq_s[tid] = g_rstd[0][off];
        mk_s[tid] = g_mean[1][off]; rk_s[tid] = g_rstd[1][off];
        mv_s[tid] = g_mean[2][off]; rv_s[tid] = g_rstd[2][off];
    }
    __syncthreads();

    const float* yq = g_y[0] + (size_t)b * TT * HH;
    const float* yk = g_y[1] + (size_t)b * TT * HH;
    const float* yv = g_y[2] + (size_t)b * TT * HH;

    // Stage 48 normalized k/v rows: global t = t0-16 .. t0+31 (clamped)
    for (int i = tid; i < 48 * 64; i += 256) {
        int row = i >> 6;
        int h   = (i & 63) << 2;
        int tg  = t0 - HALF + row;
        int tc  = tg < 0 ? 0 : (tg > TT - 1 ? TT - 1 : tg);
        float4 kk = *(const float4*)&yk[(size_t)tc * HH + h];
        float4 vv = *(const float4*)&yv[(size_t)tc * HH + h];
        float4 mk = *(float4*)&mk_s[h]; float4 rk = *(float4*)&rk_s[h];
        float4 mv = *(float4*)&mv_s[h]; float4 rv = *(float4*)&rv_s[h];
        kk.x = (kk.x - mk.x) * rk.x; kk.y = (kk.y - mk.y) * rk.y;
        kk.z = (kk.z - mk.z) * rk.z; kk.w = (kk.w - mk.w) * rk.w;
        vv.x = (vv.x - mv.x) * rv.x; vv.y = (vv.y - mv.y) * rv.y;
        vv.z = (vv.z - mv.z) * rv.z; vv.w = (vv.w - mv.w) * rv.w;
        *(float4*)&k_s[row * 256 + h] = kk;
        *(float4*)&v_s[row * 256 + h] = vv;
    }
    // Stage 16 normalized q rows
    for (int i = tid; i < 16 * 64; i += 256) {
        int row = i >> 6;
        int h   = (i & 63) << 2;
        float4 qq = *(const float4*)&yq[(size_t)(t0 + row) * HH + h];
        float4 mq = *(float4*)&mq_s[h]; float4 rq = *(float4*)&rq_s[h];
        qq.x = (qq.x - mq.x) * rq.x; qq.y = (qq.y - mq.y) * rq.y;
        qq.z = (qq.z - mq.z) * rq.z; qq.w = (qq.w - mq.w) * rq.w;
        *(float4*)&q_s[row * 256 + h] = qq;
    }
    __syncthreads();

    // Scores: warp-cooperative dot products; q cached in registers.
    const int wid  = tid >> 5;
    const int lane = tid & 31;
    for (int tl = wid; tl < TILE_T; tl += 8) {
        float4 q0 = *(float4*)&q_s[tl * 256 + (lane << 2)];
        float4 q1 = *(float4*)&q_s[tl * 256 + 128 + (lane << 2)];
        int tg = t0 + tl;
        #pragma unroll 1
        for (int w = 0; w < WIN; w++) {
            const float* kr = &k_s[(tl + w) * 256];
            float4 k0 = *(float4*)&kr[lane << 2];
            float4 k1 = *(float4*)&kr[128 + (lane << 2)];
            float d = q0.x * k0.x + q0.y * k0.y + q0.z * k0.z + q0.w * k0.w
                    + q1.x * k1.x + q1.y * k1.y + q1.z * k1.z + q1.w * k1.w;
            #pragma unroll
            for (int o = 16; o; o >>= 1) d += __shfl_xor_sync(0xffffffffu, d, o);
            if (lane == 0) {
                int idx = tg + w - HALF;
                sc[tl * 36 + w] = (idx >= 0 && idx < TT) ? d * SCALE : -INFINITY;
            }
        }
    }
    __syncthreads();

    // Softmax over the 33-wide window, one thread per t
    if (tid < TILE_T) {
        float mx = -INFINITY;
        #pragma unroll
        for (int w = 0; w < WIN; w++) mx = fmaxf(mx, sc[tid * 36 + w]);
        float ssum = 0.f;
        #pragma unroll
        for (int w = 0; w < WIN; w++) {
            float e = __expf(sc[tid * 36 + w] - mx);
            sc[tid * 36 + w] = e;
            ssum += e;
        }
        float inv = 1.0f / ssum;
        #pragma unroll
        for (int w = 0; w < WIN; w++) sc[tid * 36 + w] *= inv;
    }
    __syncthreads();

    // Output: one thread per h channel; accumulate over the tile's 16 t
    float acc = 0.f;
    #pragma unroll 1
    for (int tl = 0; tl < TILE_T; tl++) {
        #pragma unroll
        for (int w = 0; w < WIN; w++)
            acc = fmaf(sc[tl * 36 + w], v_s[(tl + w) * 256 + tid], acc);
    }
    g_partial[((size_t)b * NTILES + tile) * HH + tid] = acc;
}

// ---------------------------------------------------------------------------
// Kernel 4: out[b,h] = (1/T) * sum over tiles of partial sums
// ---------------------------------------------------------------------------
__global__ __launch_bounds__(256) void reduce_kernel(float* __restrict__ out)
{
    const int b = blockIdx.x;
    const int h = threadIdx.x;
    float s = 0.f;
    #pragma unroll 4
    for (int t = 0; t < NTILES; t++)
        s += g_partial[((size_t)b * NTILES + t) * HH + h];
    out[b * HH + h] = s * (1.0f / TT);
}

// ---------------------------------------------------------------------------
extern "C" void kernel_launch(void* const* d_in, const int* in_sizes, int n_in,
                              void* d_out, int out_size)
{
    const float* x  = (const float*)d_in[0];
    const float* Wq = (const float*)d_in[1];
    const float* bq = (const float*)d_in[2];
    const float* Wk = (const float*)d_in[3];
    const float* bk = (const float*)d_in[4];
    const float* Wv = (const float*)d_in[5];
    const float* bv = (const float*)d_in[6];
    float* out = (float*)d_out;

    const size_t attn_smem = (size_t)(112 * 256 + 16 * 36 + 6 * 256) * sizeof(float);
    // Not a stream op; safe under graph capture. Idempotent.
    cudaFuncSetAttribute(attn_kernel,
                         cudaFuncAttributeMaxDynamicSharedMemorySize,
                         (int)attn_smem);

    dim3 gemm_grid(MM / 64, HH / 64, 3);
    gemm_qkv_kernel<<<gemm_grid, 256>>>(x, Wq, bq, Wk, bk, Wv, bv);

    dim3 stat_grid(3, BB, HH / 64);
    stats_kernel<<<stat_grid, 256>>>();

    dim3 attn_grid(NTILES, BB);
    attn_kernel<<<attn_grid, 256, attn_smem>>>();

    reduce_kernel<<<BB, 256>>>(out);
}

// round 2
// speedup vs baseline: 1.2091x; 1.2091x over previous
#include <cuda_runtime.h>
#include <cuda_bf16.h>
#include <math.h>

// Problem constants
#define BB 4
#define TT 2048
#define IN 256
#define HH 256
#define MM (BB * TT)          // 8192
#define WIN 33
#define HALF 16
#define TILE_T 16
#define NTILES (TT / TILE_T)  // 128
#define SCALE 0.0625f
#define EPS 1e-5f

// GEMM tiling
#define BM 128
#define BN 64
#define BK 32
#define AS 36                 // smem row stride (bank = 4*row+col -> conflict-free frags)

// Scratch (device globals: allowed)
__device__ float g_y[3][MM * HH];
__device__ float g_mean[3][BB * HH];
__device__ float g_rstd[3][BB * HH];
__device__ float g_partial[BB * NTILES * HH];
__device__ float g_partial2[BB * 8 * HH];

__device__ __forceinline__ unsigned f2tf(float f) {
    unsigned u;
    asm("cvt.rna.tf32.f32 %0, %1;" : "=r"(u) : "f"(f));
    return u;
}

__device__ __forceinline__ void mma_tf32(float c[4], const unsigned a[4], const unsigned b[2]) {
    asm volatile(
        "mma.sync.aligned.m16n8k8.row.col.f32.tf32.tf32.f32 "
        "{%0,%1,%2,%3}, {%4,%5,%6,%7}, {%8,%9}, {%0,%1,%2,%3};"
        : "+f"(c[0]), "+f"(c[1]), "+f"(c[2]), "+f"(c[3])
        : "r"(a[0]), "r"(a[1]), "r"(a[2]), "r"(a[3]), "r"(b[0]), "r"(b[1]));
}

// ---------------------------------------------------------------------------
// Kernel 1: y[s] = x @ W[s].T + b[s]  via 3xTF32 tensor-core MMA.
// Block tile 128x64, K-step 32. 8 warps in 4(M)x2(N); warp tile 32x32.
// ---------------------------------------------------------------------------
__global__ __launch_bounds__(256) void gemm_qkv_kernel(
    const float* __restrict__ x,
    const float* __restrict__ Wq, const float* __restrict__ bq,
    const float* __restrict__ Wk, const float* __restrict__ bk,
    const float* __restrict__ Wv, const float* __restrict__ bv)
{
    const int s = blockIdx.z;
    const float* W    = (s == 0) ? Wq : (s == 1) ? Wk : Wv;
    const float* bias = (s == 0) ? bq : (s == 1) ? bk : bv;
    float* y = g_y[s];

    extern __shared__ float sm[];
    float* Ah = sm;                    // [BM][AS]
    float* Al = Ah + BM * AS;
    float* Bh = Al + BM * AS;          // [BN][AS]
    float* Bl = Bh + BN * AS;

    const int m0  = blockIdx.x * BM;
    const int n0  = blockIdx.y * BN;
    const int tid = threadIdx.x;
    const int wid = tid >> 5;
    const int lane = tid & 31;
    const int wm = (wid >> 1) * 32;    // warp M offset in tile
    const int wn = (wid & 1) * 32;     // warp N offset in tile
    const int gr = lane >> 2;          // group row 0..7
    const int gc = lane & 3;           // group col 0..3

    float acc[2][4][4] = {};           // [mi][ni][reg]

    // Prefetch registers
    float4 xa[4], wb[2];
    {
        #pragma unroll
        for (int j = 0; j < 4; j++) {
            int idx = tid + j * 256;           // float4 index over 128x8
            int r = idx >> 3, kp = (idx & 7) << 2;
            xa[j] = *(const float4*)&x[(size_t)(m0 + r) * IN + kp];
        }
        #pragma unroll
        for (int j = 0; j < 2; j++) {
            int idx = tid + j * 256;
            int r = idx >> 3, kp = (idx & 7) << 2;
            wb[j] = *(const float4*)&W[(size_t)(n0 + r) * IN + kp];
        }
    }

    #pragma unroll 1
    for (int kt = 0; kt < IN / BK; kt++) {
        // Split + store staged tile
        #pragma unroll
        for (int j = 0; j < 4; j++) {
            int idx = tid + j * 256;
            int r = idx >> 3, kp = (idx & 7) << 2;
            float f[4] = {xa[j].x, xa[j].y, xa[j].z, xa[j].w};
            #pragma unroll
            for (int e = 0; e < 4; e++) {
                float hi = __uint_as_float(f2tf(f[e]));
                Ah[r * AS + kp + e] = hi;
                Al[r * AS + kp + e] = __uint_as_float(f2tf(f[e] - hi));
            }
        }
        #pragma unroll
        for (int j = 0; j < 2; j++) {
            int idx = tid + j * 256;
            int r = idx >> 3, kp = (idx & 7) << 2;
            float f[4] = {wb[j].x, wb[j].y, wb[j].z, wb[j].w};
            #pragma unroll
            for (int e = 0; e < 4; e++) {
                float hi = __uint_as_float(f2tf(f[e]));
                Bh[r * AS + kp + e] = hi;
                Bl[r * AS + kp + e] = __uint_as_float(f2tf(f[e] - hi));
            }
        }
        __syncthreads();

        // Prefetch next k-tile (overlaps with MMA below)
        if (kt + 1 < IN / BK) {
            int k0n = (kt + 1) * BK;
            #pragma unroll
            for (int j = 0; j < 4; j++) {
                int idx = tid + j * 256;
                int r = idx >> 3, kp = (idx & 7) << 2;
                xa[j] = *(const float4*)&x[(size_t)(m0 + r) * IN + k0n + kp];
            }
            #pragma unroll
            for (int j = 0; j < 2; j++) {
                int idx = tid + j * 256;
                int r = idx >> 3, kp = (idx & 7) << 2;
                wb[j] = *(const float4*)&W[(size_t)(n0 + r) * IN + k0n + kp];
            }
        }

        // MMA over the staged BK=32 (4 sub-steps of k8)
        #pragma unroll
        for (int ks = 0; ks < 4; ks++) {
            const int k8 = ks * 8;
            unsigned ah[2][4], al[2][4], bh[4][2], bl[4][2];
            #pragma unroll
            for (int mi = 0; mi < 2; mi++) {
                int rb = wm + mi * 16;
                ah[mi][0] = __float_as_uint(Ah[(rb + gr) * AS + k8 + gc]);
                ah[mi][1] = __float_as_uint(Ah[(rb + 8 + gr) * AS + k8 + gc]);
                ah[mi][2] = __float_as_uint(Ah[(rb + gr) * AS + k8 + 4 + gc]);
                ah[mi][3] = __float_as_uint(Ah[(rb + 8 + gr) * AS + k8 + 4 + gc]);
                al[mi][0] = __float_as_uint(Al[(rb + gr) * AS + k8 + gc]);
                al[mi][1] = __float_as_uint(Al[(rb + 8 + gr) * AS + k8 + gc]);
                al[mi][2] = __float_as_uint(Al[(rb + gr) * AS + k8 + 4 + gc]);
                al[mi][3] = __float_as_uint(Al[(rb + 8 + gr) * AS + k8 + 4 + gc]);
            }
            #pragma unroll
            for (int ni = 0; ni < 4; ni++) {
                int nb = wn + ni * 8;
                bh[ni][0] = __float_as_uint(Bh[(nb + gr) * AS + k8 + gc]);
                bh[ni][1] = __float_as_uint(Bh[(nb + gr) * AS + k8 + 4 + gc]);
                bl[ni][0] = __float_as_uint(Bl[(nb + gr) * AS + k8 + gc]);
                bl[ni][1] = __float_as_uint(Bl[(nb + gr) * AS + k8 + 4 + gc]);
            }
            #pragma unroll
            for (int mi = 0; mi < 2; mi++)
                #pragma unroll
                for (int ni = 0; ni < 4; ni++) {
                    mma_tf32(acc[mi][ni], ah[mi], bl[ni]);
                    mma_tf32(acc[mi][ni], al[mi], bh[ni]);
                    mma_tf32(acc[mi][ni], ah[mi], bh[ni]);
                }
        }
        __syncthreads();
    }

    // Epilogue: add bias, store
    #pragma unroll
    for (int ni = 0; ni < 4; ni++) {
        int col = n0 + wn + ni * 8 + 2 * gc;
        float b0 = bias[col], b1 = bias[col + 1];
        #pragma unroll
        for (int mi = 0; mi < 2; mi++) {
            int row = m0 + wm + mi * 16 + gr;
            float2 o0 = make_float2(acc[mi][ni][0] + b0, acc[mi][ni][1] + b1);
            float2 o1 = make_float2(acc[mi][ni][2] + b0, acc[mi][ni][3] + b1);
            *(float2*)&y[(size_t)row * HH + col] = o0;
            *(float2*)&y[(size_t)(row + 8) * HH + col] = o1;
        }
    }
}

// ---------------------------------------------------------------------------
// Kernel 2: per-(b,h) mean / rstd over T for q,k,v.
// ---------------------------------------------------------------------------
__global__ __launch_bounds__(256) void stats_kernel()
{
    const int s  = blockIdx.x;
    const int b  = blockIdx.y;
    const int h0 = blockIdx.z * 64;
    const int ht = threadIdx.x & 63;
    const int tg = threadIdx.x >> 6;

    const float* y = g_y[s] + (size_t)b * TT * HH;
    float sum = 0.f, sq = 0.f;
    for (int t = tg; t < TT; t += 4) {
        float v = y[(size_t)t * HH + h0 + ht];
        sum += v;
        sq  = fmaf(v, v, sq);
    }
    __shared__ float ssum[4][64], ssq[4][64];
    ssum[tg][ht] = sum;
    ssq[tg][ht]  = sq;
    __syncthreads();
    if (tg == 0) {
        float S = ssum[0][ht] + ssum[1][ht] + ssum[2][ht] + ssum[3][ht];
        float Q = ssq[0][ht]  + ssq[1][ht]  + ssq[2][ht]  + ssq[3][ht];
        float m   = S * (1.0f / TT);
        float var = Q * (1.0f / TT) - m * m;
        g_mean[s][b * HH + h0 + ht] = m;
        g_rstd[s][b * HH + h0 + ht] = rsqrtf(var + EPS);
    }
}

// ---------------------------------------------------------------------------
// Kernel 3: fused normalize + windowed attention + per-tile partial sums.
// ---------------------------------------------------------------------------
__global__ __launch_bounds__(256) void attn_kernel()
{
    extern __shared__ float sm[];
    float* k_s  = sm;                    // 48*256
    float* v_s  = sm + 48 * 256;         // 48*256
    float* q_s  = sm + 96 * 256;         // 16*256
    float* sc   = sm + 112 * 256;        // 16*36
    float* st   = sc + 16 * 36;          // 6*256
    float* mq_s = st;         float* rq_s = st + 256;
    float* mk_s = st + 512;   float* rk_s = st + 768;
    float* mv_s = st + 1024;  float* rv_s = st + 1280;

    const int tile = blockIdx.x;
    const int b    = blockIdx.y;
    const int t0   = tile * TILE_T;
    const int tid  = threadIdx.x;

    {
        int off = b * HH + tid;
        mq_s[tid] = g_mean[0][off]; rq_s[tid] = g_rstd[0][off];
        mk_s[tid] = g_mean[1][off]; rk_s[tid] = g_rstd[1][off];
        mv_s[tid] = g_mean[2][off]; rv_s[tid] = g_rstd[2][off];
    }
    __syncthreads();

    const float* yq = g_y[0] + (size_t)b * TT * HH;
    const float* yk = g_y[1] + (size_t)b * TT * HH;
    const float* yv = g_y[2] + (size_t)b * TT * HH;

    for (int i = tid; i < 48 * 64; i += 256) {
        int row = i >> 6;
        int h   = (i & 63) << 2;
        int tg  = t0 - HALF + row;
        int tc  = tg < 0 ? 0 : (tg > TT - 1 ? TT - 1 : tg);
        float4 kk = *(const float4*)&yk[(size_t)tc * HH + h];
        float4 vv = *(const float4*)&yv[(size_t)tc * HH + h];
        float4 mk = *(float4*)&mk_s[h]; float4 rk = *(float4*)&rk_s[h];
        float4 mv = *(float4*)&mv_s[h]; float4 rv = *(float4*)&rv_s[h];
        kk.x = (kk.x - mk.x) * rk.x; kk.y = (kk.y - mk.y) * rk.y;
        kk.z = (kk.z - mk.z) * rk.z; kk.w = (kk.w - mk.w) * rk.w;
        vv.x = (vv.x - mv.x) * rv.x; vv.y = (vv.y - mv.y) * rv.y;
        vv.z = (vv.z - mv.z) * rv.z; vv.w = (vv.w - mv.w) * rv.w;
        *(float4*)&k_s[row * 256 + h] = kk;
        *(float4*)&v_s[row * 256 + h] = vv;
    }
    for (int i = tid; i < 16 * 64; i += 256) {
        int row = i >> 6;
        int h   = (i & 63) << 2;
        float4 qq = *(const float4*)&yq[(size_t)(t0 + row) * HH + h];
        float4 mq = *(float4*)&mq_s[h]; float4 rq = *(float4*)&rq_s[h];
        qq.x = (qq.x - mq.x) * rq.x; qq.y = (qq.y - mq.y) * rq.y;
        qq.z = (qq.z - mq.z) * rq.z; qq.w = (qq.w - mq.w) * rq.w;
        *(float4*)&q_s[row * 256 + h] = qq;
    }
    __syncthreads();

    const int wid  = tid >> 5;
    const int lane = tid & 31;
    for (int tl = wid; tl < TILE_T; tl += 8) {
        float4 q0 = *(float4*)&q_s[tl * 256 + (lane << 2)];
        float4 q1 = *(float4*)&q_s[tl * 256 + 128 + (lane << 2)];
        int tg = t0 + tl;
        #pragma unroll 1
        for (int w = 0; w < WIN; w++) {
            const float* kr = &k_s[(tl + w) * 256];
            float4 k0 = *(float4*)&kr[lane << 2];
            float4 k1 = *(float4*)&kr[128 + (lane << 2)];
            float d = q0.x * k0.x + q0.y * k0.y + q0.z * k0.z + q0.w * k0.w
                    + q1.x * k1.x + q1.y * k1.y + q1.z * k1.z + q1.w * k1.w;
            #pragma unroll
            for (int o = 16; o; o >>= 1) d += __shfl_xor_sync(0xffffffffu, d, o);
            if (lane == 0) {
                int idx = tg + w - HALF;
                sc[tl * 36 + w] = (idx >= 0 && idx < TT) ? d * SCALE : -INFINITY;
            }
        }
    }
    __syncthreads();

    if (tid < TILE_T) {
        float mx = -INFINITY;
        #pragma unroll
        for (int w = 0; w < WIN; w++) mx = fmaxf(mx, sc[tid * 36 + w]);
        float ssum = 0.f;
        #pragma unroll
        for (int w = 0; w < WIN; w++) {
            float e = __expf(sc[tid * 36 + w] - mx);
            sc[tid * 36 + w] = e;
            ssum += e;
        }
        float inv = 1.0f / ssum;
        #pragma unroll
        for (int w = 0; w < WIN; w++) sc[tid * 36 + w] *= inv;
    }
    __syncthreads();

    float acc = 0.f;
    #pragma unroll 1
    for (int tl = 0; tl < TILE_T; tl++) {
        #pragma unroll
        for (int w = 0; w < WIN; w++)
            acc = fmaf(sc[tl * 36 + w], v_s[(tl + w) * 256 + tid], acc);
    }
    g_partial[((size_t)b * NTILES + tile) * HH + tid] = acc;
}

// ---------------------------------------------------------------------------
// Kernel 4a/4b: two-stage deterministic mean over tiles.
// ---------------------------------------------------------------------------
__global__ __launch_bounds__(256) void reduce1_kernel()
{
    const int b   = blockIdx.x;
    const int seg = blockIdx.y;
    const int h   = threadIdx.x;
    float s = 0.f;
    #pragma unroll
    for (int t = 0; t < 16; t++)
        s += g_partial[((size_t)b * NTILES + seg * 16 + t) * HH + h];
    g_partial2[((size_t)b * 8 + seg) * HH + h] = s;
}

__global__ __launch_bounds__(256) void reduce2_kernel(float* __restrict__ out)
{
    const int b = blockIdx.x;
    const int h = threadIdx.x;
    float s = 0.f;
    #pragma unroll
    for (int g = 0; g < 8; g++)
        s += g_partial2[((size_t)b * 8 + g) * HH + h];
    out[b * HH + h] = s * (1.0f / TT);
}

// ---------------------------------------------------------------------------
extern "C" void kernel_launch(void* const* d_in, const int* in_sizes, int n_in,
                              void* d_out, int out_size)
{
    const float* x  = (const float*)d_in[0];
    const float* Wq = (const float*)d_in[1];
    const float* bq = (const float*)d_in[2];
    const float* Wk = (const float*)d_in[3];
    const float* bk = (const float*)d_in[4];
    const float* Wv = (const float*)d_in[5];
    const float* bv = (const float*)d_in[6];
    float* out = (float*)d_out;

    const size_t gemm_smem = (size_t)(2 * BM * AS + 2 * BN * AS) * sizeof(float);
    const size_t attn_smem = (size_t)(112 * 256 + 16 * 36 + 6 * 256) * sizeof(float);
    cudaFuncSetAttribute(gemm_qkv_kernel,
                         cudaFuncAttributeMaxDynamicSharedMemorySize, (int)gemm_smem);
    cudaFuncSetAttribute(attn_kernel,
                         cudaFuncAttributeMaxDynamicSharedMemorySize, (int)attn_smem);

    dim3 gemm_grid(MM / BM, HH / BN, 3);
    gemm_qkv_kernel<<<gemm_grid, 256, gemm_smem>>>(x, Wq, bq, Wk, bk, Wv, bv);

    dim3 stat_grid(3, BB, HH / 64);
    stats_kernel<<<stat_grid, 256>>>();

    dim3 attn_grid(NTILES, BB);
    attn_kernel<<<attn_grid, 256, attn_smem>>>();

    reduce1_kernel<<<dim3(BB, 8), 256>>>();
    reduce2_kernel<<<BB, 256>>>(out);
}

// round 3
// speedup vs baseline: 1.6826x; 1.3916x over previous
#include <cuda_runtime.h>
#include <cuda_bf16.h>
#include <math.h>

// Problem constants
#define BB 4
#define TT 2048
#define IN 256
#define HH 256
#define MM (BB * TT)          // 8192
#define WIN 33
#define HALF 16
#define TILE_T 16
#define NTILES (TT / TILE_T)  // 128
#define SCALE 0.0625f
#define EPS 1e-5f

// GEMM tiling
#define BM 128
#define BN 64
#define BK 32
#define AS 36                 // smem row stride (bank = 4*row+col -> conflict-free frags)

// Scratch (device globals: allowed)
__device__ float g_y[3][MM * HH];
__device__ float g_statp[3][MM / BM][HH][2];   // per (s, m-block, col): sum, sumsq
__device__ float g_mean[3][BB * HH];
__device__ float g_rstd[3][BB * HH];
__device__ float g_partial[BB * NTILES * HH];

__device__ __forceinline__ unsigned f2tf(float f) {
    unsigned u;
    asm("cvt.rna.tf32.f32 %0, %1;" : "=r"(u) : "f"(f));
    return u;
}

__device__ __forceinline__ void mma_tf32(float c[4], const unsigned a[4], const unsigned b[2]) {
    asm volatile(
        "mma.sync.aligned.m16n8k8.row.col.f32.tf32.tf32.f32 "
        "{%0,%1,%2,%3}, {%4,%5,%6,%7}, {%8,%9}, {%0,%1,%2,%3};"
        : "+f"(c[0]), "+f"(c[1]), "+f"(c[2]), "+f"(c[3])
        : "r"(a[0]), "r"(a[1]), "r"(a[2]), "r"(a[3]), "r"(b[0]), "r"(b[1]));
}

// ---------------------------------------------------------------------------
// Kernel 1: y[s] = x @ W[s].T + b[s] via 3xTF32 MMA; epilogue also emits
// per-block column (sum, sumsq) partials for instance-norm stats.
// ---------------------------------------------------------------------------
__global__ __launch_bounds__(256) void gemm_qkv_kernel(
    const float* __restrict__ x,
    const float* __restrict__ Wq, const float* __restrict__ bq,
    const float* __restrict__ Wk, const float* __restrict__ bk,
    const float* __restrict__ Wv, const float* __restrict__ bv)
{
    const int s = blockIdx.z;
    const float* W    = (s == 0) ? Wq : (s == 1) ? Wk : Wv;
    const float* bias = (s == 0) ? bq : (s == 1) ? bk : bv;
    float* y = g_y[s];

    extern __shared__ float sm[];
    float* Ah = sm;
    float* Al = Ah + BM * AS;
    float* Bh = Al + BM * AS;
    float* Bl = Bh + BN * AS;

    const int m0  = blockIdx.x * BM;
    const int n0  = blockIdx.y * BN;
    const int tid = threadIdx.x;
    const int wid = tid >> 5;
    const int lane = tid & 31;
    const int wm = (wid >> 1) * 32;
    const int wn = (wid & 1) * 32;
    const int gr = lane >> 2;
    const int gc = lane & 3;

    float acc[2][4][4] = {};

    float4 xa[4], wb[2];
    #pragma unroll
    for (int j = 0; j < 4; j++) {
        int idx = tid + j * 256;
        int r = idx >> 3, kp = (idx & 7) << 2;
        xa[j] = *(const float4*)&x[(size_t)(m0 + r) * IN + kp];
    }
    #pragma unroll
    for (int j = 0; j < 2; j++) {
        int idx = tid + j * 256;
        int r = idx >> 3, kp = (idx & 7) << 2;
        wb[j] = *(const float4*)&W[(size_t)(n0 + r) * IN + kp];
    }

    #pragma unroll 1
    for (int kt = 0; kt < IN / BK; kt++) {
        #pragma unroll
        for (int j = 0; j < 4; j++) {
            int idx = tid + j * 256;
            int r = idx >> 3, kp = (idx & 7) << 2;
            float f[4] = {xa[j].x, xa[j].y, xa[j].z, xa[j].w};
            #pragma unroll
            for (int e = 0; e < 4; e++) {
                float hi = __uint_as_float(f2tf(f[e]));
                Ah[r * AS + kp + e] = hi;
                Al[r * AS + kp + e] = __uint_as_float(f2tf(f[e] - hi));
            }
        }
        #pragma unroll
        for (int j = 0; j < 2; j++) {
            int idx = tid + j * 256;
            int r = idx >> 3, kp = (idx & 7) << 2;
            float f[4] = {wb[j].x, wb[j].y, wb[j].z, wb[j].w};
            #pragma unroll
            for (int e = 0; e < 4; e++) {
                float hi = __uint_as_float(f2tf(f[e]));
                Bh[r * AS + kp + e] = hi;
                Bl[r * AS + kp + e] = __uint_as_float(f2tf(f[e] - hi));
            }
        }
        __syncthreads();

        if (kt + 1 < IN / BK) {
            int k0n = (kt + 1) * BK;
            #pragma unroll
            for (int j = 0; j < 4; j++) {
                int idx = tid + j * 256;
                int r = idx >> 3, kp = (idx & 7) << 2;
                xa[j] = *(const float4*)&x[(size_t)(m0 + r) * IN + k0n + kp];
            }
            #pragma unroll
            for (int j = 0; j < 2; j++) {
                int idx = tid + j * 256;
                int r = idx >> 3, kp = (idx & 7) << 2;
                wb[j] = *(const float4*)&W[(size_t)(n0 + r) * IN + k0n + kp];
            }
        }

        #pragma unroll
        for (int ks = 0; ks < 4; ks++) {
            const int k8 = ks * 8;
            unsigned ah[2][4], al[2][4], bh[4][2], bl[4][2];
            #pragma unroll
            for (int mi = 0; mi < 2; mi++) {
                int rb = wm + mi * 16;
                ah[mi][0] = __float_as_uint(Ah[(rb + gr) * AS + k8 + gc]);
                ah[mi][1] = __float_as_uint(Ah[(rb + 8 + gr) * AS + k8 + gc]);
                ah[mi][2] = __float_as_uint(Ah[(rb + gr) * AS + k8 + 4 + gc]);
                ah[mi][3] = __float_as_uint(Ah[(rb + 8 + gr) * AS + k8 + 4 + gc]);
                al[mi][0] = __float_as_uint(Al[(rb + gr) * AS + k8 + gc]);
                al[mi][1] = __float_as_uint(Al[(rb + 8 + gr) * AS + k8 + gc]);
                al[mi][2] = __float_as_uint(Al[(rb + gr) * AS + k8 + 4 + gc]);
                al[mi][3] = __float_as_uint(Al[(rb + 8 + gr) * AS + k8 + 4 + gc]);
            }
            #pragma unroll
            for (int ni = 0; ni < 4; ni++) {
                int nb = wn + ni * 8;
                bh[ni][0] = __float_as_uint(Bh[(nb + gr) * AS + k8 + gc]);
                bh[ni][1] = __float_as_uint(Bh[(nb + gr) * AS + k8 + 4 + gc]);
                bl[ni][0] = __float_as_uint(Bl[(nb + gr) * AS + k8 + gc]);
                bl[ni][1] = __float_as_uint(Bl[(nb + gr) * AS + k8 + 4 + gc]);
            }
            #pragma unroll
            for (int mi = 0; mi < 2; mi++)
                #pragma unroll
                for (int ni = 0; ni < 4; ni++) {
                    mma_tf32(acc[mi][ni], ah[mi], bl[ni]);
                    mma_tf32(acc[mi][ni], al[mi], bh[ni]);
                    mma_tf32(acc[mi][ni], ah[mi], bh[ni]);
                }
        }
        __syncthreads();
    }

    // Epilogue: bias + store + per-column stat partials
    float scol[8], qcol[8];
    #pragma unroll
    for (int ni = 0; ni < 4; ni++) {
        int col = n0 + wn + ni * 8 + 2 * gc;
        float b0 = bias[col], b1 = bias[col + 1];
        float ss0 = 0.f, ss1 = 0.f, qq0 = 0.f, qq1 = 0.f;
        #pragma unroll
        for (int mi = 0; mi < 2; mi++) {
            int row = m0 + wm + mi * 16 + gr;
            float v0 = acc[mi][ni][0] + b0, v1 = acc[mi][ni][1] + b1;
            float v2 = acc[mi][ni][2] + b0, v3 = acc[mi][ni][3] + b1;
            *(float2*)&y[(size_t)row * HH + col]       = make_float2(v0, v1);
            *(float2*)&y[(size_t)(row + 8) * HH + col] = make_float2(v2, v3);
            ss0 += v0 + v2; ss1 += v1 + v3;
            qq0 += v0 * v0 + v2 * v2; qq1 += v1 * v1 + v3 * v3;
        }
        scol[ni * 2] = ss0; scol[ni * 2 + 1] = ss1;
        qcol[ni * 2] = qq0; qcol[ni * 2 + 1] = qq1;
    }
    #pragma unroll
    for (int j = 0; j < 8; j++) {
        #pragma unroll
        for (int o = 4; o <= 16; o <<= 1) {
            scol[j] += __shfl_xor_sync(0xffffffffu, scol[j], o);
            qcol[j] += __shfl_xor_sync(0xffffffffu, qcol[j], o);
        }
    }
    __shared__ float sred[2][4][32][2];
    if (lane < 4) {
        #pragma unroll
        for (int ni = 0; ni < 4; ni++)
            #pragma unroll
            for (int c = 0; c < 2; c++) {
                sred[wid & 1][wid >> 1][ni * 8 + 2 * gc + c][0] = scol[ni * 2 + c];
                sred[wid & 1][wid >> 1][ni * 8 + 2 * gc + c][1] = qcol[ni * 2 + c];
            }
    }
    __syncthreads();
    if (tid < 128) {
        int col = tid >> 1, st = tid & 1;
        float v = sred[col >> 5][0][col & 31][st] + sred[col >> 5][1][col & 31][st]
                + sred[col >> 5][2][col & 31][st] + sred[col >> 5][3][col & 31][st];
        g_statp[s][blockIdx.x][n0 + col][st] = v;
    }
}

// ---------------------------------------------------------------------------
// Kernel 2: finalize per-(b,h) mean / rstd from GEMM partials.
// ---------------------------------------------------------------------------
__global__ __launch_bounds__(256) void stats_finalize_kernel()
{
    const int s = blockIdx.x;
    const int b = blockIdx.y;
    const int h = threadIdx.x;
    float S = 0.f, Q = 0.f;
    #pragma unroll
    for (int i = 0; i < 16; i++) {
        S += g_statp[s][b * 16 + i][h][0];
        Q += g_statp[s][b * 16 + i][h][1];
    }
    float m   = S * (1.0f / TT);
    float var = Q * (1.0f / TT) - m * m;
    g_mean[s][b * HH + h] = m;
    g_rstd[s][b * HH + h] = rsqrtf(var + EPS);
}

// ---------------------------------------------------------------------------
// Kernel 3: fused normalize + windowed attention + per-tile partial sums.
// smem ~107 KB -> 2 blocks/SM. Output phase via collapsed coeff[r].
// ---------------------------------------------------------------------------
__global__ __launch_bounds__(256) void attn_kernel()
{
    extern __shared__ float sm[];
    float* k_s   = sm;                       // 48*256
    float* v_s   = sm + 48 * 256;            // 48*256
    float* sc    = sm + 96 * 256;            // 16*36
    float* coeff = sc + 16 * 36;             // 64 (48 used)
    float* st    = coeff + 64;               // 6*256
    float* mq_s = st;         float* rq_s = st + 256;
    float* mk_s = st + 512;   float* rk_s = st + 768;
    float* mv_s = st + 1024;  float* rv_s = st + 1280;

    const int tile = blockIdx.x;
    const int b    = blockIdx.y;
    const int t0   = tile * TILE_T;
    const int tid  = threadIdx.x;

    {
        int off = b * HH + tid;
        mq_s[tid] = g_mean[0][off]; rq_s[tid] = g_rstd[0][off];
        mk_s[tid] = g_mean[1][off]; rk_s[tid] = g_rstd[1][off];
        mv_s[tid] = g_mean[2][off]; rv_s[tid] = g_rstd[2][off];
    }
    __syncthreads();

    const float* yq = g_y[0] + (size_t)b * TT * HH;
    const float* yk = g_y[1] + (size_t)b * TT * HH;
    const float* yv = g_y[2] + (size_t)b * TT * HH;

    // Stage 48 normalized k/v rows (t = t0-16 .. t0+31, clamped)
    for (int i = tid; i < 48 * 64; i += 256) {
        int row = i >> 6;
        int h   = (i & 63) << 2;
        int tg  = t0 - HALF + row;
        int tc  = tg < 0 ? 0 : (tg > TT - 1 ? TT - 1 : tg);
        float4 kk = *(const float4*)&yk[(size_t)tc * HH + h];
        float4 vv = *(const float4*)&yv[(size_t)tc * HH + h];
        float4 mk = *(float4*)&mk_s[h]; float4 rk = *(float4*)&rk_s[h];
        float4 mv = *(float4*)&mv_s[h]; float4 rv = *(float4*)&rv_s[h];
        kk.x = (kk.x - mk.x) * rk.x; kk.y = (kk.y - mk.y) * rk.y;
        kk.z = (kk.z - mk.z) * rk.z; kk.w = (kk.w - mk.w) * rk.w;
        vv.x = (vv.x - mv.x) * rv.x; vv.y = (vv.y - mv.y) * rv.y;
        vv.z = (vv.z - mv.z) * rv.z; vv.w = (vv.w - mv.w) * rv.w;
        *(float4*)&k_s[row * 256 + h] = kk;
        *(float4*)&v_s[row * 256 + h] = vv;
    }
    __syncthreads();

    // Scores: warp per t; q loaded straight from gmem and normalized in regs
    const int wid  = tid >> 5;
    const int lane = tid & 31;
    for (int tl = wid; tl < TILE_T; tl += 8) {
        const float* qr = &yq[(size_t)(t0 + tl) * HH];
        float4 q0 = *(const float4*)&qr[lane << 2];
        float4 q1 = *(const float4*)&qr[128 + (lane << 2)];
        float4 mq0 = *(float4*)&mq_s[lane << 2];       float4 rq0 = *(float4*)&rq_s[lane << 2];
        float4 mq1 = *(float4*)&mq_s[128 + (lane << 2)]; float4 rq1 = *(float4*)&rq_s[128 + (lane << 2)];
        q0.x = (q0.x - mq0.x) * rq0.x; q0.y = (q0.y - mq0.y) * rq0.y;
        q0.z = (q0.z - mq0.z) * rq0.z; q0.w = (q0.w - mq0.w) * rq0.w;
        q1.x = (q1.x - mq1.x) * rq1.x; q1.y = (q1.y - mq1.y) * rq1.y;
        q1.z = (q1.z - mq1.z) * rq1.z; q1.w = (q1.w - mq1.w) * rq1.w;
        int tg = t0 + tl;
        #pragma unroll 1
        for (int w = 0; w < WIN; w++) {
            const float* kr = &k_s[(tl + w) * 256];
            float4 k0 = *(float4*)&kr[lane << 2];
            float4 k1 = *(float4*)&kr[128 + (lane << 2)];
            float d = q0.x * k0.x + q0.y * k0.y + q0.z * k0.z + q0.w * k0.w
                    + q1.x * k1.x + q1.y * k1.y + q1.z * k1.z + q1.w * k1.w;
            #pragma unroll
            for (int o = 16; o; o >>= 1) d += __shfl_xor_sync(0xffffffffu, d, o);
            if (lane == 0) {
                int idx = tg + w - HALF;
                sc[tl * 36 + w] = (idx >= 0 && idx < TT) ? d * SCALE : -INFINITY;
            }
        }
    }
    __syncthreads();

    // Softmax per t (16 threads)
    if (tid < TILE_T) {
        float mx = -INFINITY;
        #pragma unroll
        for (int w = 0; w < WIN; w++) mx = fmaxf(mx, sc[tid * 36 + w]);
        float ssum = 0.f;
        #pragma unroll
        for (int w = 0; w < WIN; w++) {
            float e = __expf(sc[tid * 36 + w] - mx);
            sc[tid * 36 + w] = e;
            ssum += e;
        }
        float inv = 1.0f / ssum;
        #pragma unroll
        for (int w = 0; w < WIN; w++) sc[tid * 36 + w] *= inv;
    }
    __syncthreads();

    // Collapse probs by kv row: coeff[r] = sum_tl p[tl][r-tl]
    if (tid < 48) {
        float c = 0.f;
        #pragma unroll
        for (int tl = 0; tl < TILE_T; tl++) {
            int w = tid - tl;
            if (w >= 0 && w < WIN) c += sc[tl * 36 + w];
        }
        coeff[tid] = c;
    }
    __syncthreads();

    // Output: 48 FMA per thread (was 528)
    float acc = 0.f;
    #pragma unroll
    for (int r = 0; r < 48; r++)
        acc = fmaf(coeff[r], v_s[r * 256 + tid], acc);
    g_partial[((size_t)b * NTILES + tile) * HH + tid] = acc;
}

// ---------------------------------------------------------------------------
// Kernel 4: single-launch deterministic mean over tiles.
// ---------------------------------------------------------------------------
__global__ __launch_bounds__(1024) void reduce_kernel(float* __restrict__ out)
{
    __shared__ float s4[4][256];
    const int b = blockIdx.x;
    const int g = threadIdx.x >> 8;
    const int h = threadIdx.x & 255;
    float s = 0.f;
    #pragma unroll 4
    for (int t = 0; t < 32; t++)
        s += g_partial[((size_t)b * NTILES + g * 32 + t) * HH + h];
    s4[g][h] = s;
    __syncthreads();
    if (threadIdx.x < 256) {
        float v = s4[0][h] + s4[1][h] + s4[2][h] + s4[3][h];
        out[b * HH + h] = v * (1.0f / TT);
    }
}

// ---------------------------------------------------------------------------
extern "C" void kernel_launch(void* const* d_in, const int* in_sizes, int n_in,
                              void* d_out, int out_size)
{
    const float* x  = (const float*)d_in[0];
    const float* Wq = (const float*)d_in[1];
    const float* bq = (const float*)d_in[2];
    const float* Wk = (const float*)d_in[3];
    const float* bk = (const float*)d_in[4];
    const float* Wv = (const float*)d_in[5];
    const float* bv = (const float*)d_in[6];
    float* out = (float*)d_out;

    const size_t gemm_smem = (size_t)(2 * BM * AS + 2 * BN * AS) * sizeof(float);
    const size_t attn_smem = (size_t)(96 * 256 + 16 * 36 + 64 + 6 * 256) * sizeof(float);
    cudaFuncSetAttribute(gemm_qkv_kernel,
                         cudaFuncAttributeMaxDynamicSharedMemorySize, (int)gemm_smem);
    cudaFuncSetAttribute(attn_kernel,
                         cudaFuncAttributeMaxDynamicSharedMemorySize, (int)attn_smem);

    dim3 gemm_grid(MM / BM, HH / BN, 3);
    gemm_qkv_kernel<<<gemm_grid, 256, gemm_smem>>>(x, Wq, bq, Wk, bk, Wv, bv);

    stats_finalize_kernel<<<dim3(3, BB), 256>>>();

    dim3 attn_grid(NTILES, BB);
    attn_kernel<<<attn_grid, 256, attn_smem>>>();

    reduce_kernel<<<BB, 1024>>>(out);
}